// round 15
// baseline (speedup 1.0000x reference)
#include <cuda_runtime.h>

// Problem constants
#define BF_TOT  (16 * 4096)      // B * F = 65536
#define PAIRS   6                // 12 data symbols -> 6 STBC pairs
#define NBITS0  3145728          // BF_TOT * 48
#define NGAIN   786432           // BF_TOT * 12
#define THREADS 256
#define WARP_STRIDE 520          // float4 per warp stage: 8 pair-regions x 65
#define SMEM_BYTES (8 * WARP_STRIDE * 16)   // 66560 B per CTA

typedef unsigned long long u64;

// ---- packed f32x2 primitives (sm_103a) ----
__device__ __forceinline__ u64 pk(float lo, float hi){
    u64 r; asm("mov.b64 %0, {%1, %2};" : "=l"(r) : "f"(lo), "f"(hi)); return r;
}
__device__ __forceinline__ void unpk(u64 v, float& lo, float& hi){
    asm("mov.b64 {%0, %1}, %2;" : "=f"(lo), "=f"(hi) : "l"(v));
}
__device__ __forceinline__ float usum(u64 v){ float lo, hi; unpk(v, lo, hi); return lo + hi; }
__device__ __forceinline__ u64 fmul2(u64 a, u64 b){
    u64 d; asm("mul.rn.f32x2 %0, %1, %2;" : "=l"(d) : "l"(a), "l"(b)); return d;
}
__device__ __forceinline__ u64 fadd2(u64 a, u64 b){
    u64 d; asm("add.rn.f32x2 %0, %1, %2;" : "=l"(d) : "l"(a), "l"(b)); return d;
}
__device__ __forceinline__ u64 fsub2(u64 a, u64 b){
    u64 d; asm("sub.rn.f32x2 %0, %1, %2;" : "=l"(d) : "l"(a), "l"(b)); return d;
}
__device__ __forceinline__ u64 ffma2(u64 a, u64 b, u64 c){
    u64 d; asm("fma.rn.f32x2 %0, %1, %2, %3;" : "=l"(d) : "l"(a), "l"(b), "l"(c)); return d;
}
__device__ __forceinline__ u64 dot2(u64 a, u64 b, u64 c, u64 d){
    return ffma2(c, d, fmul2(a, b));
}
__device__ __forceinline__ u64 dot4(u64 a,u64 b,u64 c,u64 d,u64 e,u64 f,u64 g,u64 h){
    return ffma2(g, h, ffma2(e, f, ffma2(c, d, fmul2(a, b))));
}

// ---- scalar complex helpers (solve path) ----
__device__ __forceinline__ float2 cmul (float2 a, float2 b){ return make_float2(a.x*b.x - a.y*b.y, a.x*b.y + a.y*b.x); }
__device__ __forceinline__ float2 cmulc(float2 a, float2 b){ return make_float2(a.x*b.x + a.y*b.y, a.x*b.y - a.y*b.x); }
__device__ __forceinline__ float2 cadd (float2 a, float2 b){ return make_float2(a.x+b.x, a.y+b.y); }
__device__ __forceinline__ float2 csub (float2 a, float2 b){ return make_float2(a.x-b.x, a.y-b.y); }
__device__ __forceinline__ float2 cscl (float2 a, float s){ return make_float2(a.x*s, a.y*s); }
__device__ __forceinline__ float2 cconj(float2 a){ return make_float2(a.x, -a.y); }

// 16-QAM Gray hard decision with configurable magnitude threshold.
__device__ __forceinline__ void hd16(float2 y, float thr, float2& pt, int& bits){
    const float C1 = 0.31622776601683794f;   // 1/sqrt(10)
    const float C3 = 0.9486832980505138f;    // 3/sqrt(10)
    int b0 = (y.x < 0.0f);
    int b1 = (y.y < 0.0f);
    int b2 = (fabsf(y.x) > thr);
    int b3 = (fabsf(y.y) > thr);
    float xi = b2 ? C3 : C1; if (b0) xi = -xi;
    float xq = b3 ? C3 : C1; if (b1) xq = -xq;
    pt = make_float2(xi, xq);
    bits = b0 | (b1 << 1) | (b2 << 2) | (b3 << 3);
}

// 2-step xor butterfly over each 4-lane group (result broadcast within group)
#define RED4(v) do { \
    v += __shfl_xor_sync(0xffffffffu, v, 1);  \
    v += __shfl_xor_sync(0xffffffffu, v, 2);  \
} while (0)

// Load + pack one antenna-pair unit (antennas a0_, a0_+1) from the stage.
// Declares the 16 packed u64 (A=symA raw, B=symB raw) and summed channel.
#define UNIT_LOAD_PACK(a0_) \
    float4 rA0 = my[(a0_)],        rA1 = my[(a0_)+1];        \
    float4 rB0 = my[16+(a0_)],     rB1 = my[16+(a0_)+1];     \
    float4 iA0 = my[32+(a0_)],     iA1 = my[32+(a0_)+1];     \
    float4 iB0 = my[48+(a0_)],     iB1 = my[48+(a0_)+1];     \
    u64 AaR=pk(rA0.x,rA1.x), AaI=pk(iA0.x,iA1.x);            \
    u64 AbR=pk(rA0.y,rA1.y), AbI=pk(iA0.y,iA1.y);            \
    u64 AcR=pk(rA0.z,rA1.z), AcI=pk(iA0.z,iA1.z);            \
    u64 AdR=pk(rA0.w,rA1.w), AdI=pk(iA0.w,iA1.w);            \
    u64 BaR=pk(rB0.x,rB1.x), BaI=pk(iB0.x,iB1.x);            \
    u64 BbR=pk(rB0.y,rB1.y), BbI=pk(iB0.y,iB1.y);            \
    u64 BcR=pk(rB0.z,rB1.z), BcI=pk(iB0.z,iB1.z);            \
    u64 BdR=pk(rB0.w,rB1.w), BdI=pk(iB0.w,iB1.w);

// Per-unit packed y (unit un: antennas 4j+2un, 4j+2un+1 = float4 halves)
#define UNIT_Y(un) \
    u64 yAr = (un==0)? pk(yAR.x,yAR.y) : pk(yAR.z,yAR.w);    \
    u64 yAi = (un==0)? pk(yAI.x,yAI.y) : pk(yAI.z,yAI.w);    \
    u64 yBr = (un==0)? pk(yBR.x,yBR.y) : pk(yBR.z,yBR.w);    \
    u64 yBi = (un==0)? pk(yBI.x,yBI.y) : pk(yBI.z,yBI.w);

__global__ void __launch_bounds__(THREADS, 3)
mc_ncjt_kernel(const float* __restrict__ ryR, const float* __restrict__ ryI,
               const float* __restrict__ hR,  const float* __restrict__ hI,
               float* __restrict__ out)
{
    extern __shared__ float4 smbuf[];   // [8 warps][8 pairs][65 float4]

    const int tid  = threadIdx.x;
    const int lane = tid & 31;
    const int w    = tid >> 5;
    const int q    = lane >> 2;       // pair within warp (8 pairs/warp)
    const int j    = lane & 3;        // 4 lanes/pair; lane owns antennas 4j..4j+3

    const float4* hR4  = (const float4*)hR;
    const float4* hI4  = (const float4*)hI;
    const float4* ryR4 = (const float4*)ryR;
    const float4* ryI4 = (const float4*)ryI;

    float4* stg = smbuf + w * WARP_STRIDE;
    const unsigned warpP = (blockIdx.x * 8u + (unsigned)w) * 8u;

    // ---- my pair ----
    const unsigned P  = warpP + (unsigned)q;
    const unsigned bf = P / PAIRS;
    const unsigned p  = P - bf * PAIRS;
    const unsigned sA = 2u*p + (p >= 1u) + (p >= 5u);   // data pairs (0,1)(3,4)(5,6)(7,8)(9,10)(12,13)

    // ---- y loads: one float4 = 4 adjacent antennas (64B contiguous/group) ----
    float4 yAR = __ldcs(ryR4 + bf*56u + sA*4u + j);
    float4 yAI = __ldcs(ryI4 + bf*56u + sA*4u + j);
    float4 yBR = __ldcs(ryR4 + bf*56u + (sA+1u)*4u + j);
    float4 yBI = __ldcs(ryI4 + bf*56u + (sA+1u)*4u + j);

    // ---- cooperative stage fill: per pair i, chunk = 512B (both symbols) ----
    #pragma unroll
    for (int i = 0; i < 8; ++i) {
        unsigned Pi  = warpP + (unsigned)i;
        unsigned bfi = Pi / PAIRS, pi = Pi - bfi * PAIRS;
        unsigned sAi = 2u*pi + (pi >= 1u) + (pi >= 5u);
        unsigned src = bfi*224u + sAi*16u + (unsigned)lane;   // lane covers sA(0-15), sB(16-31)
        stg[i*65 + lane]      = __ldcs(hR4 + src);
        stg[i*65 + 32 + lane] = __ldcs(hI4 + src);
    }
    __syncwarp();

    const float4* my = stg + q * 65;

    // ---- Gram/rhs over this lane's 4 antennas (2 packed units) ----
    float al=0.f, be=0.f, gx=0.f, gy=0.f, dxx=0.f, dyy=0.f;
    float u0x=0.f,u0y=0.f,u1x=0.f,u1y=0.f,u2x=0.f,u2y=0.f,u3x=0.f,u3y=0.f;

    #pragma unroll
    for (int un = 0; un < 2; ++un) {
        const int a0 = 4*j + 2*un;
        UNIT_LOAD_PACK(a0);
        u64 aR=fadd2(AaR,BaR), aI=fadd2(AaI,BaI);
        u64 bR=fadd2(AbR,BbR), bI=fadd2(AbI,BbI);
        u64 cR=fadd2(AcR,BcR), cI=fadd2(AcI,BcI);
        u64 dR=fadd2(AdR,BdR), dI=fadd2(AdI,BdI);
        UNIT_Y(un);
        al  += usum(dot4(aR,aR, aI,aI, bR,bR, bI,bI));
        be  += usum(dot4(cR,cR, cI,cI, dR,dR, dI,dI));
        gx  += usum(dot4(aR,cR, aI,cI, bR,dR, bI,dI));
        gy  += usum(fsub2(dot2(aR,cI, bI,dR), dot2(aI,cR, bR,dI)));
        dxx += usum(fsub2(dot2(aR,dR, aI,dI), dot2(bR,cR, bI,cI)));
        dyy += usum(fsub2(dot2(aR,dI, bR,cI), dot2(aI,dR, bI,cR)));
        u0x += usum(dot4(aR,yAr, aI,yAi, bR,yBr, bI,yBi));
        u0y += usum(fsub2(dot2(aR,yAi, bI,yBr), dot2(aI,yAr, bR,yBi)));
        u1x += usum(fsub2(dot2(bR,yAr, bI,yAi), dot2(aR,yBr, aI,yBi)));
        u1y += usum(fsub2(dot2(bR,yAi, aR,yBi), dot2(bI,yAr, aI,yBr)));
        u2x += usum(dot4(cR,yAr, cI,yAi, dR,yBr, dI,yBi));
        u2y += usum(fsub2(dot2(cR,yAi, dI,yBr), dot2(cI,yAr, dR,yBi)));
        u3x += usum(fsub2(dot2(dR,yAr, dI,yAi), dot2(cR,yBr, cI,yBi)));
        u3y += usum(fsub2(dot2(dR,yAi, cR,yBi), dot2(dI,yAr, cI,yBr)));
    }

    // ---- 4-lane reductions (2 levels, broadcast within pair group) ----
    RED4(al);  RED4(be);
    RED4(gx);  RED4(gy);  RED4(dxx); RED4(dyy);
    RED4(u0x); RED4(u0y); RED4(u1x); RED4(u1y);
    RED4(u2x); RED4(u2y); RED4(u3x); RED4(u3y);

    float alpha = al, beta = be;
    float2 gam = make_float2(gx, gy), del = make_float2(dxx, dyy);
    float2 u0 = make_float2(u0x,u0y), u1 = make_float2(u1x,u1y);
    float2 u2 = make_float2(u2x,u2y), u3 = make_float2(u3x,u3y);

    // ---- closed-form Schur solve (scaled: Ghat=4G, uhat=2u -> shat=s/2) ----
    const float e      = gam.x*gam.x + gam.y*gam.y + del.x*del.x + del.y*del.y;
    const float invden = 1.0f / (alpha * beta - e);
    const float invA   = 1.0f / alpha;
    float2 t2 = csub(cscl(u2, alpha), csub(cmulc(gam, u0), cmul(del, u1)));
    float2 t3 = csub(cscl(u3, alpha), cadd(cmulc(del, u0), cmul(gam, u1)));
    float2 s2 = cscl(t2, invden);
    float2 s3 = cscl(t3, invden);
    float2 s0 = cscl(csub(u0, cadd(cmul(gam, s2), cmul(del, s3))), invA);
    float2 s1 = cscl(cadd(u1, csub(cmul(cconj(del), s2), cmul(cconj(gam), s3))), invA);

    const bool c0 = (alpha >= beta);

    const float THALF = 0.31622776601683794f;   // (2/sqrt(10)) / 2
    const float TFULL = 0.6324555320336759f;    //  2/sqrt(10)
    float2 px0, px1, px2, px3; int ib0, ib1, ib2, ib3;
    hd16(s0, THALF, px0, ib0); hd16(s1, THALF, px1, ib1);
    hd16(s2, THALF, px2, ib2); hd16(s3, THALF, px3, ib3);

    float2 bx0 = c0 ? px0 : px2;     // better-stream decisions (sym A, sym B)
    float2 bx1 = c0 ? px1 : px3;

    u64 B0R = pk(bx0.x, bx0.x), B0I = pk(bx0.y, bx0.y);
    u64 B1R = pk(bx1.x, bx1.x), B1I = pk(bx1.y, bx1.y);

    // force re-reads from the stage (raw values were consumed; don't cache)
    asm volatile("" ::: "memory");

    // ---- SIC over this lane's 4 antennas (re-read + re-pack from stage) ----
    float t0x=0.f, t0y=0.f, t1x=0.f, t1y=0.f;
    #pragma unroll
    for (int un = 0; un < 2; ++un) {
        const int a0 = 4*j + 2*un;
        UNIT_LOAD_PACK(a0);
        UNIT_Y(un);
        u64 cA0R,cA0I,cA1R,cA1I, cB0R,cB0I,cB1R,cB1I, g0R,g0I,g1R,g1I;
        if (c0) {
            cA0R=AaR; cA0I=AaI; cA1R=AbR; cA1I=AbI;
            cB0R=BaR; cB0I=BaI; cB1R=BbR; cB1I=BbI;
            g0R=fadd2(AcR,BcR); g0I=fadd2(AcI,BcI);
            g1R=fadd2(AdR,BdR); g1I=fadd2(AdI,BdI);
        } else {
            cA0R=AcR; cA0I=AcI; cA1R=AdR; cA1I=AdI;
            cB0R=BcR; cB0I=BcI; cB1R=BdR; cB1I=BdI;
            g0R=fadd2(AaR,BaR); g0I=fadd2(AaI,BaI);
            g1R=fadd2(AbR,BbR); g1I=fadd2(AbI,BbI);
        }
        // eA = cbA0*bx0 + cbA1*bx1
        u64 eAr = fsub2(dot2(cA0R,B0R, cA1R,B1R), dot2(cA0I,B0I, cA1I,B1I));
        u64 eAi = dot4(cA0R,B0I, cA0I,B0R, cA1R,B1I, cA1I,B1R);
        // eB = cbB0*(-conj(bx1)) + cbB1*conj(bx0)
        u64 eBr = fsub2(dot2(cB1R,B0R, cB1I,B0I), dot2(cB0R,B1R, cB0I,B1I));
        u64 eBi = fsub2(dot2(cB0R,B1I, cB1I,B0R), dot2(cB0I,B1R, cB1R,B0I));
        u64 rnAr = fsub2(yAr, eAr), rnAi = fsub2(yAi, eAi);
        u64 rnBr = fsub2(yBr, eBr), rnBi = fsub2(yBi, eBi);
        // t0 = conj(g0)*rnA + g1*conj(rnB); t1 = conj(g1)*rnA - g0*conj(rnB)
        t0x += usum(dot4(g0R,rnAr, g0I,rnAi, g1R,rnBr, g1I,rnBi));
        t0y += usum(fsub2(dot2(g0R,rnAi, g1I,rnBr), dot2(g0I,rnAr, g1R,rnBi)));
        t1x += usum(fsub2(dot2(g1R,rnAr, g1I,rnAi), dot2(g0R,rnBr, g0I,rnBi)));
        t1y += usum(fsub2(dot2(g1R,rnAi, g0R,rnBi), dot2(g1I,rnAr, g0I,rnBr)));
    }
    RED4(t0x); RED4(t0y); RED4(t1x); RED4(t1y);

    // worse g summed = 2x avg; true gain = betahat/4 -> y = 2*that/betahat
    const float invG = 2.0f / (c0 ? beta : alpha);
    float2 pn0, pn1; int ibn0, ibn1;
    hd16(cscl(make_float2(t0x,t0y), invG), TFULL, pn0, ibn0);
    hd16(cscl(make_float2(t1x,t1y), invG), TFULL, pn1, ibn1);

    // final stream assignments
    const int bb0 = c0 ? ib0 : ib2;   // better bits sym A
    const int bb1 = c0 ? ib1 : ib3;   // better bits sym B
    const int b0A = c0 ? bb0  : ibn0; // bits0 (stream 0)
    const int b0B = c0 ? bb1  : ibn1;
    const int b1A = c0 ? ibn0 : bb0;  // bits1 (stream 1)
    const int b1B = c0 ? ibn1 : bb1;

    // ---- outputs: bits0 | bits1 | gains0 | gains1 | nvar ----
    float* bits0 = out;
    float* bits1 = out + NBITS0;
    float* g0out = out + 2 * NBITS0;
    float* g1out = out + 2 * NBITS0 + NGAIN;

    const unsigned sym0 = 2u * p;
    const unsigned bbase = bf*48u + sym0*4u;     // float4-aligned

    {   // all 4 lanes write one float4 of bits
        int nib = (j == 0) ? b0A : (j == 1) ? b0B : (j == 2) ? b1A : b1B;
        float4 v = make_float4((float)( nib       & 1), (float)((nib >> 1) & 1),
                               (float)((nib >> 2) & 1), (float)((nib >> 3) & 1));
        float* base = (j < 2) ? bits0 : bits1;
        *(float4*)(base + bbase + ((j & 1) << 2)) = v;
    }
    if (j == 0) {
        float g = alpha * 0.25f;      // true gain (sum -> avg scale)
        *(float2*)(g0out + bf*12u + sym0) = make_float2(g, g);
    } else if (j == 1) {
        float g = beta * 0.25f;
        *(float2*)(g1out + bf*12u + sym0) = make_float2(g, g);
    }

    if (blockIdx.x == 0 && tid == 0)
        out[2 * (NBITS0 + NGAIN)] = 0.4f;    // nvar scalar
}

extern "C" void kernel_launch(void* const* d_in, const int* in_sizes, int n_in,
                              void* d_out, int out_size) {
    const float* ryR = (const float*)d_in[0];
    const float* ryI = (const float*)d_in[1];
    const float* hR  = (const float*)d_in[2];
    const float* hI  = (const float*)d_in[3];
    float* out = (float*)d_out;

    // dynamic smem opt-in (idempotent; safe under graph capture)
    cudaFuncSetAttribute(mc_ncjt_kernel,
                         cudaFuncAttributeMaxDynamicSharedMemorySize, SMEM_BYTES);

    // total pairs = 393216; 8 pairs/warp, 8 warps/block -> 6144 blocks
    const int total_pairs = BF_TOT * PAIRS;
    const int blocks = total_pairs / 64;
    mc_ncjt_kernel<<<blocks, THREADS, SMEM_BYTES>>>(ryR, ryI, hR, hI, out);
}

// round 16
// speedup vs baseline: 1.2296x; 1.2296x over previous
#include <cuda_runtime.h>

// Problem constants
#define BF_TOT  (16 * 4096)      // B * F = 65536
#define PAIRS   6                // 12 data symbols -> 6 STBC pairs
#define NBITS0  3145728          // BF_TOT * 48
#define NGAIN   786432           // BF_TOT * 12

typedef unsigned long long u64;

// ---- packed f32x2 primitives (sm_103a) ----
__device__ __forceinline__ u64 pk(float lo, float hi){
    u64 r; asm("mov.b64 %0, {%1, %2};" : "=l"(r) : "f"(lo), "f"(hi)); return r;
}
__device__ __forceinline__ void unpk(u64 v, float& lo, float& hi){
    asm("mov.b64 {%0, %1}, %2;" : "=f"(lo), "=f"(hi) : "l"(v));
}
__device__ __forceinline__ float usum(u64 v){ float lo, hi; unpk(v, lo, hi); return lo + hi; }
__device__ __forceinline__ u64 fmul2(u64 a, u64 b){
    u64 d; asm("mul.rn.f32x2 %0, %1, %2;" : "=l"(d) : "l"(a), "l"(b)); return d;
}
__device__ __forceinline__ u64 fadd2(u64 a, u64 b){
    u64 d; asm("add.rn.f32x2 %0, %1, %2;" : "=l"(d) : "l"(a), "l"(b)); return d;
}
__device__ __forceinline__ u64 fsub2(u64 a, u64 b){
    u64 d; asm("sub.rn.f32x2 %0, %1, %2;" : "=l"(d) : "l"(a), "l"(b)); return d;
}
__device__ __forceinline__ u64 ffma2(u64 a, u64 b, u64 c){
    u64 d; asm("fma.rn.f32x2 %0, %1, %2, %3;" : "=l"(d) : "l"(a), "l"(b), "l"(c)); return d;
}
__device__ __forceinline__ u64 dot2(u64 a, u64 b, u64 c, u64 d){
    return ffma2(c, d, fmul2(a, b));
}
__device__ __forceinline__ u64 dot4(u64 a,u64 b,u64 c,u64 d,u64 e,u64 f,u64 g,u64 h){
    return ffma2(g, h, ffma2(e, f, ffma2(c, d, fmul2(a, b))));
}

// ---- scalar complex helpers (solve path) ----
__device__ __forceinline__ float2 cmul (float2 a, float2 b){ return make_float2(a.x*b.x - a.y*b.y, a.x*b.y + a.y*b.x); }
__device__ __forceinline__ float2 cmulc(float2 a, float2 b){ return make_float2(a.x*b.x + a.y*b.y, a.x*b.y - a.y*b.x); }
__device__ __forceinline__ float2 cadd (float2 a, float2 b){ return make_float2(a.x+b.x, a.y+b.y); }
__device__ __forceinline__ float2 csub (float2 a, float2 b){ return make_float2(a.x-b.x, a.y-b.y); }
__device__ __forceinline__ float2 cscl (float2 a, float s){ return make_float2(a.x*s, a.y*s); }
__device__ __forceinline__ float2 cconj(float2 a){ return make_float2(a.x, -a.y); }

// 16-QAM Gray hard decision with configurable magnitude threshold.
__device__ __forceinline__ void hd16(float2 y, float thr, float2& pt, int& bits){
    const float C1 = 0.31622776601683794f;   // 1/sqrt(10)
    const float C3 = 0.9486832980505138f;    // 3/sqrt(10)
    int b0 = (y.x < 0.0f);
    int b1 = (y.y < 0.0f);
    int b2 = (fabsf(y.x) > thr);
    int b3 = (fabsf(y.y) > thr);
    float xi = b2 ? C3 : C1; if (b0) xi = -xi;
    float xq = b3 ? C3 : C1; if (b1) xq = -xq;
    pt = make_float2(xi, xq);
    bits = b0 | (b1 << 1) | (b2 << 2) | (b3 << 3);
}

// 3-step xor butterfly over each 8-lane group (result broadcast within group)
#define RED8(v) do { \
    v += __shfl_xor_sync(0xffffffffu, v, 1);  \
    v += __shfl_xor_sync(0xffffffffu, v, 2);  \
    v += __shfl_xor_sync(0xffffffffu, v, 4);  \
} while (0)

__global__ void __launch_bounds__(256, 3)
mc_ncjt_kernel(const float* __restrict__ ryR, const float* __restrict__ ryI,
               const float* __restrict__ hR,  const float* __restrict__ hI,
               float* __restrict__ out)
{
    // Packed raw channel stash: slot-major [8][256] ulonglong2 -> conflict-free
    // LDS/STS.128. Slots: symA(aRI,bRI,cRI,dRI)=0..3, symB(...)=4..7.  32 KB.
    __shared__ ulonglong2 pst[8][256];

    const int tid  = threadIdx.x;
    const int lane = tid & 31;
    const unsigned warp = blockIdx.x * 8u + (unsigned)(tid >> 5);
    const int q    = lane >> 3;       // pair within warp (4 pairs/warp)
    const int j    = lane & 7;        // 8 lanes/pair; lane owns antennas 2j, 2j+1

    const unsigned P  = warp * 4u + (unsigned)q;   // global STBC-pair index
    const unsigned bf = P / PAIRS;
    const unsigned p  = P - bf * PAIRS;

    // data-symbol pairs: (0,1)(3,4)(5,6)(7,8)(9,10)(12,13)
    const unsigned sA = 2u*p + (p >= 1u) + (p >= 5u);

    const float4* hR4  = (const float4*)hR;
    const float4* hI4  = (const float4*)hI;
    const float2* ryR2 = (const float2*)ryR;
    const float2* ryI2 = (const float2*)ryI;
    const unsigned iA = bf*224u + sA*16u + 2u*(unsigned)j;   // float4 index
    const unsigned iB = iA + 16u;
    const unsigned yA2 = bf*112u + sA*8u + (unsigned)j;      // float2 index
    const unsigned yB2 = yA2 + 8u;

    // ---- streaming loads; float2 y loads ARE the packed lanes (2j, 2j+1) ----
    float2 fyAr = __ldcs(ryR2 + yA2), fyAi = __ldcs(ryI2 + yA2);
    float2 fyBr = __ldcs(ryR2 + yB2), fyBi = __ldcs(ryI2 + yB2);
    u64 yAr = pk(fyAr.x, fyAr.y), yAi = pk(fyAi.x, fyAi.y);
    u64 yBr = pk(fyBr.x, fyBr.y), yBi = pk(fyBi.x, fyBi.y);

    float4 hrA0 = __ldcs(hR4 + iA),  hrA1 = __ldcs(hR4 + iA + 1);
    float4 hiA0 = __ldcs(hI4 + iA),  hiA1 = __ldcs(hI4 + iA + 1);
    float4 hrB0 = __ldcs(hR4 + iB),  hrB1 = __ldcs(hR4 + iB + 1);
    float4 hiB0 = __ldcs(hI4 + iB),  hiB1 = __ldcs(hI4 + iB + 1);

    // ---- pack per-antenna pairs: (antenna 2j, antenna 2j+1) as f32x2 ----
    u64 pAaR = pk(hrA0.x, hrA1.x), pAaI = pk(hiA0.x, hiA1.x);
    u64 pAbR = pk(hrA0.y, hrA1.y), pAbI = pk(hiA0.y, hiA1.y);
    u64 pAcR = pk(hrA0.z, hrA1.z), pAcI = pk(hiA0.z, hiA1.z);
    u64 pAdR = pk(hrA0.w, hrA1.w), pAdI = pk(hiA0.w, hiA1.w);
    u64 pBaR = pk(hrB0.x, hrB1.x), pBaI = pk(hiB0.x, hiB1.x);
    u64 pBbR = pk(hrB0.y, hrB1.y), pBbI = pk(hiB0.y, hiB1.y);
    u64 pBcR = pk(hrB0.z, hrB1.z), pBcI = pk(hiB0.z, hiB1.z);
    u64 pBdR = pk(hrB0.w, hrB1.w), pBdI = pk(hiB0.w, hiB1.w);

    // stash raw packed channel for the SIC pass (frees the registers)
    pst[0][tid] = make_ulonglong2(pAaR, pAaI);
    pst[1][tid] = make_ulonglong2(pAbR, pAbI);
    pst[2][tid] = make_ulonglong2(pAcR, pAcI);
    pst[3][tid] = make_ulonglong2(pAdR, pAdI);
    pst[4][tid] = make_ulonglong2(pBaR, pBaI);
    pst[5][tid] = make_ulonglong2(pBbR, pBbI);
    pst[6][tid] = make_ulonglong2(pBcR, pBcI);
    pst[7][tid] = make_ulonglong2(pBdR, pBdI);

    // summed channel (2x average; scale folded into thresholds/invG/gains)
    u64 aR = fadd2(pAaR, pBaR), aI = fadd2(pAaI, pBaI);
    u64 bR = fadd2(pAbR, pBbR), bI = fadd2(pAbI, pBbI);
    u64 cR = fadd2(pAcR, pBcR), cI = fadd2(pAcI, pBcI);
    u64 dR = fadd2(pAdR, pBdR), dI = fadd2(pAdI, pBdI);

    // ---- packed Gram/rhs (both antennas at once), unpack to scalars ----
    float alpha = usum(dot4(aR,aR, aI,aI, bR,bR, bI,bI));
    float beta  = usum(dot4(cR,cR, cI,cI, dR,dR, dI,dI));
    float2 gam, del, u0, u1, u2, u3;
    gam.x = usum(dot4(aR,cR, aI,cI, bR,dR, bI,dI));
    gam.y = usum(fsub2(dot2(aR,cI, bI,dR), dot2(aI,cR, bR,dI)));
    del.x = usum(fsub2(dot2(aR,dR, aI,dI), dot2(bR,cR, bI,cI)));
    del.y = usum(fsub2(dot2(aR,dI, bR,cI), dot2(aI,dR, bI,cR)));
    u0.x  = usum(dot4(aR,yAr, aI,yAi, bR,yBr, bI,yBi));
    u0.y  = usum(fsub2(dot2(aR,yAi, bI,yBr), dot2(aI,yAr, bR,yBi)));
    u1.x  = usum(fsub2(dot2(bR,yAr, bI,yAi), dot2(aR,yBr, aI,yBi)));
    u1.y  = usum(fsub2(dot2(bR,yAi, aR,yBi), dot2(bI,yAr, aI,yBr)));
    u2.x  = usum(dot4(cR,yAr, cI,yAi, dR,yBr, dI,yBi));
    u2.y  = usum(fsub2(dot2(cR,yAi, dI,yBr), dot2(cI,yAr, dR,yBi)));
    u3.x  = usum(fsub2(dot2(dR,yAr, dI,yAi), dot2(cR,yBr, cI,yBi)));
    u3.y  = usum(fsub2(dot2(dR,yAi, cR,yBi), dot2(dI,yAr, cI,yBr)));

    // ---- 8-lane reductions (broadcast within pair group) ----
    RED8(alpha); RED8(beta);
    RED8(gam.x); RED8(gam.y); RED8(del.x); RED8(del.y);
    RED8(u0.x);  RED8(u0.y);  RED8(u1.x);  RED8(u1.y);
    RED8(u2.x);  RED8(u2.y);  RED8(u3.x);  RED8(u3.y);

    // ---- closed-form Schur solve (scaled: Ghat=4G, uhat=2u -> shat=s/2) ----
    const float e      = gam.x*gam.x + gam.y*gam.y + del.x*del.x + del.y*del.y;
    const float invden = 1.0f / (alpha * beta - e);
    const float invA   = 1.0f / alpha;
    float2 t2 = csub(cscl(u2, alpha), csub(cmulc(gam, u0), cmul(del, u1)));
    float2 t3 = csub(cscl(u3, alpha), cadd(cmulc(del, u0), cmul(gam, u1)));
    float2 s2 = cscl(t2, invden);
    float2 s3 = cscl(t3, invden);
    float2 s0 = cscl(csub(u0, cadd(cmul(gam, s2), cmul(del, s3))), invA);
    float2 s1 = cscl(cadd(u1, csub(cmul(cconj(del), s2), cmul(cconj(gam), s3))), invA);

    const bool c0 = (alpha >= beta);

    const float THALF = 0.31622776601683794f;   // (2/sqrt(10)) / 2
    const float TFULL = 0.6324555320336759f;    //  2/sqrt(10)
    float2 px0, px1, px2, px3; int ib0, ib1, ib2, ib3;
    hd16(s0, THALF, px0, ib0); hd16(s1, THALF, px1, ib1);
    hd16(s2, THALF, px2, ib2); hd16(s3, THALF, px3, ib3);

    float2 bx0 = c0 ? px0 : px2;     // better-stream decisions (sym A, sym B)
    float2 bx1 = c0 ? px1 : px3;

    u64 B0R = pk(bx0.x, bx0.x), B0I = pk(bx0.y, bx0.y);
    u64 B1R = pk(bx1.x, bx1.x), B1I = pk(bx1.y, bx1.y);

    // ---- SIC (packed): reload raw channel from smem, cancel, recombine ----
    ulonglong2 cbA0 = pst[c0 ? 0 : 2][tid];
    ulonglong2 cbA1 = pst[c0 ? 1 : 3][tid];
    ulonglong2 cbB0 = pst[c0 ? 4 : 6][tid];
    ulonglong2 cbB1 = pst[c0 ? 5 : 7][tid];
    ulonglong2 wA0  = pst[c0 ? 2 : 0][tid];
    ulonglong2 wA1  = pst[c0 ? 3 : 1][tid];
    ulonglong2 wB0  = pst[c0 ? 6 : 4][tid];
    ulonglong2 wB1  = pst[c0 ? 7 : 5][tid];
    u64 g0R = fadd2(wA0.x, wB0.x), g0I = fadd2(wA0.y, wB0.y);
    u64 g1R = fadd2(wA1.x, wB1.x), g1I = fadd2(wA1.y, wB1.y);

    // eA = cbA0*bx0 + cbA1*bx1
    u64 eAr = fsub2(dot2(cbA0.x,B0R, cbA1.x,B1R), dot2(cbA0.y,B0I, cbA1.y,B1I));
    u64 eAi = dot4(cbA0.x,B0I, cbA0.y,B0R, cbA1.x,B1I, cbA1.y,B1R);
    // eB = cbB0*(-conj(bx1)) + cbB1*conj(bx0)
    u64 eBr = fsub2(dot2(cbB1.x,B0R, cbB1.y,B0I), dot2(cbB0.x,B1R, cbB0.y,B1I));
    u64 eBi = fsub2(dot2(cbB0.x,B1I, cbB1.y,B0R), dot2(cbB0.y,B1R, cbB1.x,B0I));
    u64 rnAr = fsub2(yAr, eAr), rnAi = fsub2(yAi, eAi);
    u64 rnBr = fsub2(yBr, eBr), rnBi = fsub2(yBi, eBi);

    // t0 = conj(g0)*rnA + g1*conj(rnB); t1 = conj(g1)*rnA - g0*conj(rnB)
    float2 t0, t1;
    t0.x = usum(dot4(g0R,rnAr, g0I,rnAi, g1R,rnBr, g1I,rnBi));
    t0.y = usum(fsub2(dot2(g0R,rnAi, g1I,rnBr), dot2(g0I,rnAr, g1R,rnBi)));
    t1.x = usum(fsub2(dot2(g1R,rnAr, g1I,rnAi), dot2(g0R,rnBr, g0I,rnBi)));
    t1.y = usum(fsub2(dot2(g1R,rnAi, g0R,rnBi), dot2(g1I,rnAr, g0I,rnBr)));
    RED8(t0.x); RED8(t0.y); RED8(t1.x); RED8(t1.y);

    // g summed = 2x avg; true gain = betahat/4 -> y = 2*that/betahat
    const float invG = 2.0f / (c0 ? beta : alpha);
    float2 pn0, pn1; int ibn0, ibn1;
    hd16(cscl(t0, invG), TFULL, pn0, ibn0);
    hd16(cscl(t1, invG), TFULL, pn1, ibn1);

    // final stream assignments
    const int bb0 = c0 ? ib0 : ib2;   // better bits sym A
    const int bb1 = c0 ? ib1 : ib3;   // better bits sym B
    const int b0A = c0 ? bb0  : ibn0; // bits0 (stream 0)
    const int b0B = c0 ? bb1  : ibn1;
    const int b1A = c0 ? ibn0 : bb0;  // bits1 (stream 1)
    const int b1B = c0 ? ibn1 : bb1;

    // ---- outputs (streaming stores): bits0 | bits1 | gains0 | gains1 | nvar ----
    float* bits0 = out;
    float* bits1 = out + NBITS0;
    float* g0out = out + 2 * NBITS0;
    float* g1out = out + 2 * NBITS0 + NGAIN;

    const unsigned sym0 = 2u * p;
    const unsigned bbase = bf*48u + sym0*4u;     // float4-aligned

    if (j < 4) {
        int nib = (j == 0) ? b0A : (j == 1) ? b0B : (j == 2) ? b1A : b1B;
        float4 v = make_float4((float)( nib       & 1), (float)((nib >> 1) & 1),
                               (float)((nib >> 2) & 1), (float)((nib >> 3) & 1));
        float* base = (j < 2) ? bits0 : bits1;
        __stcs((float4*)(base + bbase + ((j & 1) << 2)), v);
    } else if (j == 4) {
        float g = alpha * 0.25f;      // true gain (sum -> avg scale)
        __stcs((float2*)(g0out + bf*12u + sym0), make_float2(g, g));
    } else if (j == 5) {
        float g = beta * 0.25f;
        __stcs((float2*)(g1out + bf*12u + sym0), make_float2(g, g));
    }

    if (blockIdx.x == 0 && tid == 0)
        out[2 * (NBITS0 + NGAIN)] = 0.4f;    // nvar scalar
}

extern "C" void kernel_launch(void* const* d_in, const int* in_sizes, int n_in,
                              void* d_out, int out_size) {
    const float* ryR = (const float*)d_in[0];
    const float* ryI = (const float*)d_in[1];
    const float* hR  = (const float*)d_in[2];
    const float* hI  = (const float*)d_in[3];
    float* out = (float*)d_out;

    // total pairs = 65536*6 = 393216; 4 pairs/warp, 8 warps/block -> 12288 blocks
    const int total_pairs = BF_TOT * PAIRS;
    const int blocks = total_pairs / 32;   // 32 pairs per 256-thread block
    mc_ncjt_kernel<<<blocks, 256>>>(ryR, ryI, hR, hI, out);
}

// round 17
// speedup vs baseline: 1.2332x; 1.0030x over previous
#include <cuda_runtime.h>

// Problem constants
#define BF_TOT  (16 * 4096)      // B * F = 65536
#define PAIRS   6                // 12 data symbols -> 6 STBC pairs
#define NBITS0  3145728          // BF_TOT * 48
#define NGAIN   786432           // BF_TOT * 12

typedef unsigned long long u64;

// ---- packed f32x2 primitives (sm_103a) ----
__device__ __forceinline__ u64 pk(float lo, float hi){
    u64 r; asm("mov.b64 %0, {%1, %2};" : "=l"(r) : "f"(lo), "f"(hi)); return r;
}
__device__ __forceinline__ void unpk(u64 v, float& lo, float& hi){
    asm("mov.b64 {%0, %1}, %2;" : "=f"(lo), "=f"(hi) : "l"(v));
}
__device__ __forceinline__ float usum(u64 v){ float lo, hi; unpk(v, lo, hi); return lo + hi; }
__device__ __forceinline__ u64 fmul2(u64 a, u64 b){
    u64 d; asm("mul.rn.f32x2 %0, %1, %2;" : "=l"(d) : "l"(a), "l"(b)); return d;
}
__device__ __forceinline__ u64 fadd2(u64 a, u64 b){
    u64 d; asm("add.rn.f32x2 %0, %1, %2;" : "=l"(d) : "l"(a), "l"(b)); return d;
}
__device__ __forceinline__ u64 fsub2(u64 a, u64 b){
    u64 d; asm("sub.rn.f32x2 %0, %1, %2;" : "=l"(d) : "l"(a), "l"(b)); return d;
}
__device__ __forceinline__ u64 ffma2(u64 a, u64 b, u64 c){
    u64 d; asm("fma.rn.f32x2 %0, %1, %2, %3;" : "=l"(d) : "l"(a), "l"(b), "l"(c)); return d;
}
__device__ __forceinline__ u64 dot2(u64 a, u64 b, u64 c, u64 d){
    return ffma2(c, d, fmul2(a, b));
}
__device__ __forceinline__ u64 dot4(u64 a,u64 b,u64 c,u64 d,u64 e,u64 f,u64 g,u64 h){
    return ffma2(g, h, ffma2(e, f, ffma2(c, d, fmul2(a, b))));
}

// 256-bit global load (sm_100+): two consecutive float4s in one LDG.
__device__ __forceinline__ void ldg256(const float4* p, float4& a, float4& b){
    asm("ld.global.v8.f32 {%0,%1,%2,%3,%4,%5,%6,%7}, [%8];"
        : "=f"(a.x), "=f"(a.y), "=f"(a.z), "=f"(a.w),
          "=f"(b.x), "=f"(b.y), "=f"(b.z), "=f"(b.w)
        : "l"(p));
}

// ---- scalar complex helpers (solve path) ----
__device__ __forceinline__ float2 cmul (float2 a, float2 b){ return make_float2(a.x*b.x - a.y*b.y, a.x*b.y + a.y*b.x); }
__device__ __forceinline__ float2 cmulc(float2 a, float2 b){ return make_float2(a.x*b.x + a.y*b.y, a.x*b.y - a.y*b.x); }
__device__ __forceinline__ float2 cadd (float2 a, float2 b){ return make_float2(a.x+b.x, a.y+b.y); }
__device__ __forceinline__ float2 csub (float2 a, float2 b){ return make_float2(a.x-b.x, a.y-b.y); }
__device__ __forceinline__ float2 cscl (float2 a, float s){ return make_float2(a.x*s, a.y*s); }
__device__ __forceinline__ float2 cconj(float2 a){ return make_float2(a.x, -a.y); }

// 16-QAM Gray hard decision with configurable magnitude threshold.
__device__ __forceinline__ void hd16(float2 y, float thr, float2& pt, int& bits){
    const float C1 = 0.31622776601683794f;   // 1/sqrt(10)
    const float C3 = 0.9486832980505138f;    // 3/sqrt(10)
    int b0 = (y.x < 0.0f);
    int b1 = (y.y < 0.0f);
    int b2 = (fabsf(y.x) > thr);
    int b3 = (fabsf(y.y) > thr);
    float xi = b2 ? C3 : C1; if (b0) xi = -xi;
    float xq = b3 ? C3 : C1; if (b1) xq = -xq;
    pt = make_float2(xi, xq);
    bits = b0 | (b1 << 1) | (b2 << 2) | (b3 << 3);
}

// 3-step xor butterfly over each 8-lane group (result broadcast within group)
#define RED8(v) do { \
    v += __shfl_xor_sync(0xffffffffu, v, 1);  \
    v += __shfl_xor_sync(0xffffffffu, v, 2);  \
    v += __shfl_xor_sync(0xffffffffu, v, 4);  \
} while (0)

__global__ void __launch_bounds__(256, 3)
mc_ncjt_kernel(const float* __restrict__ ryR, const float* __restrict__ ryI,
               const float* __restrict__ hR,  const float* __restrict__ hI,
               float* __restrict__ out)
{
    // Packed raw channel stash: slot-major [8][256] ulonglong2 -> conflict-free
    // LDS/STS.128. Slots: symA(aRI,bRI,cRI,dRI)=0..3, symB(...)=4..7.  32 KB.
    __shared__ ulonglong2 pst[8][256];

    const int tid  = threadIdx.x;
    const int lane = tid & 31;
    const unsigned warp = blockIdx.x * 8u + (unsigned)(tid >> 5);
    const int q    = lane >> 3;       // pair within warp (4 pairs/warp)
    const int j    = lane & 7;        // 8 lanes/pair; lane owns antennas 2j, 2j+1

    const unsigned P  = warp * 4u + (unsigned)q;   // global STBC-pair index
    const unsigned bf = P / PAIRS;
    const unsigned p  = P - bf * PAIRS;

    // data-symbol pairs: (0,1)(3,4)(5,6)(7,8)(9,10)(12,13)
    const unsigned sA = 2u*p + (p >= 1u) + (p >= 5u);

    const float4* hR4  = (const float4*)hR;
    const float4* hI4  = (const float4*)hI;
    const float2* ryR2 = (const float2*)ryR;
    const float2* ryI2 = (const float2*)ryI;
    const unsigned iA = bf*224u + sA*16u + 2u*(unsigned)j;   // float4 index (even -> 32B aligned)
    const unsigned iB = iA + 16u;
    const unsigned yA2 = bf*112u + sA*8u + (unsigned)j;      // float2 index
    const unsigned yB2 = yA2 + 8u;

    // ---- loads; float2 y loads ARE the packed lanes (antennas 2j, 2j+1) ----
    float2 fyAr = __ldcs(ryR2 + yA2), fyAi = __ldcs(ryI2 + yA2);
    float2 fyBr = __ldcs(ryR2 + yB2), fyBi = __ldcs(ryI2 + yB2);
    u64 yAr = pk(fyAr.x, fyAr.y), yAi = pk(fyAi.x, fyAi.y);
    u64 yBr = pk(fyBr.x, fyBr.y), yBi = pk(fyBi.x, fyBi.y);

    // 256-bit h loads: both antennas' float4s in one LDG each
    float4 hrA0, hrA1, hiA0, hiA1, hrB0, hrB1, hiB0, hiB1;
    ldg256(hR4 + iA, hrA0, hrA1);
    ldg256(hI4 + iA, hiA0, hiA1);
    ldg256(hR4 + iB, hrB0, hrB1);
    ldg256(hI4 + iB, hiB0, hiB1);

    // ---- pack per-antenna pairs: (antenna 2j, antenna 2j+1) as f32x2 ----
    u64 pAaR = pk(hrA0.x, hrA1.x), pAaI = pk(hiA0.x, hiA1.x);
    u64 pAbR = pk(hrA0.y, hrA1.y), pAbI = pk(hiA0.y, hiA1.y);
    u64 pAcR = pk(hrA0.z, hrA1.z), pAcI = pk(hiA0.z, hiA1.z);
    u64 pAdR = pk(hrA0.w, hrA1.w), pAdI = pk(hiA0.w, hiA1.w);
    u64 pBaR = pk(hrB0.x, hrB1.x), pBaI = pk(hiB0.x, hiB1.x);
    u64 pBbR = pk(hrB0.y, hrB1.y), pBbI = pk(hiB0.y, hiB1.y);
    u64 pBcR = pk(hrB0.z, hrB1.z), pBcI = pk(hiB0.z, hiB1.z);
    u64 pBdR = pk(hrB0.w, hrB1.w), pBdI = pk(hiB0.w, hiB1.w);

    // stash raw packed channel for the SIC pass (frees the registers)
    pst[0][tid] = make_ulonglong2(pAaR, pAaI);
    pst[1][tid] = make_ulonglong2(pAbR, pAbI);
    pst[2][tid] = make_ulonglong2(pAcR, pAcI);
    pst[3][tid] = make_ulonglong2(pAdR, pAdI);
    pst[4][tid] = make_ulonglong2(pBaR, pBaI);
    pst[5][tid] = make_ulonglong2(pBbR, pBbI);
    pst[6][tid] = make_ulonglong2(pBcR, pBcI);
    pst[7][tid] = make_ulonglong2(pBdR, pBdI);

    // summed channel (2x average; scale folded into thresholds/invG/gains)
    u64 aR = fadd2(pAaR, pBaR), aI = fadd2(pAaI, pBaI);
    u64 bR = fadd2(pAbR, pBbR), bI = fadd2(pAbI, pBbI);
    u64 cR = fadd2(pAcR, pBcR), cI = fadd2(pAcI, pBcI);
    u64 dR = fadd2(pAdR, pBdR), dI = fadd2(pAdI, pBdI);

    // ---- packed Gram/rhs (both antennas at once), unpack to scalars ----
    float alpha = usum(dot4(aR,aR, aI,aI, bR,bR, bI,bI));
    float beta  = usum(dot4(cR,cR, cI,cI, dR,dR, dI,dI));
    float2 gam, del, u0, u1, u2, u3;
    gam.x = usum(dot4(aR,cR, aI,cI, bR,dR, bI,dI));
    gam.y = usum(fsub2(dot2(aR,cI, bI,dR), dot2(aI,cR, bR,dI)));
    del.x = usum(fsub2(dot2(aR,dR, aI,dI), dot2(bR,cR, bI,cI)));
    del.y = usum(fsub2(dot2(aR,dI, bR,cI), dot2(aI,dR, bI,cR)));
    u0.x  = usum(dot4(aR,yAr, aI,yAi, bR,yBr, bI,yBi));
    u0.y  = usum(fsub2(dot2(aR,yAi, bI,yBr), dot2(aI,yAr, bR,yBi)));
    u1.x  = usum(fsub2(dot2(bR,yAr, bI,yAi), dot2(aR,yBr, aI,yBi)));
    u1.y  = usum(fsub2(dot2(bR,yAi, aR,yBi), dot2(bI,yAr, aI,yBr)));
    u2.x  = usum(dot4(cR,yAr, cI,yAi, dR,yBr, dI,yBi));
    u2.y  = usum(fsub2(dot2(cR,yAi, dI,yBr), dot2(cI,yAr, dR,yBi)));
    u3.x  = usum(fsub2(dot2(dR,yAr, dI,yAi), dot2(cR,yBr, cI,yBi)));
    u3.y  = usum(fsub2(dot2(dR,yAi, cR,yBi), dot2(dI,yAr, cI,yBr)));

    // ---- 8-lane reductions (broadcast within pair group) ----
    RED8(alpha); RED8(beta);
    RED8(gam.x); RED8(gam.y); RED8(del.x); RED8(del.y);
    RED8(u0.x);  RED8(u0.y);  RED8(u1.x);  RED8(u1.y);
    RED8(u2.x);  RED8(u2.y);  RED8(u3.x);  RED8(u3.y);

    // ---- closed-form Schur solve (scaled: Ghat=4G, uhat=2u -> shat=s/2) ----
    const float e      = gam.x*gam.x + gam.y*gam.y + del.x*del.x + del.y*del.y;
    const float invden = 1.0f / (alpha * beta - e);
    const float invA   = 1.0f / alpha;
    float2 t2 = csub(cscl(u2, alpha), csub(cmulc(gam, u0), cmul(del, u1)));
    float2 t3 = csub(cscl(u3, alpha), cadd(cmulc(del, u0), cmul(gam, u1)));
    float2 s2 = cscl(t2, invden);
    float2 s3 = cscl(t3, invden);
    float2 s0 = cscl(csub(u0, cadd(cmul(gam, s2), cmul(del, s3))), invA);
    float2 s1 = cscl(cadd(u1, csub(cmul(cconj(del), s2), cmul(cconj(gam), s3))), invA);

    const bool c0 = (alpha >= beta);

    const float THALF = 0.31622776601683794f;   // (2/sqrt(10)) / 2
    const float TFULL = 0.6324555320336759f;    //  2/sqrt(10)
    float2 px0, px1, px2, px3; int ib0, ib1, ib2, ib3;
    hd16(s0, THALF, px0, ib0); hd16(s1, THALF, px1, ib1);
    hd16(s2, THALF, px2, ib2); hd16(s3, THALF, px3, ib3);

    float2 bx0 = c0 ? px0 : px2;     // better-stream decisions (sym A, sym B)
    float2 bx1 = c0 ? px1 : px3;

    u64 B0R = pk(bx0.x, bx0.x), B0I = pk(bx0.y, bx0.y);
    u64 B1R = pk(bx1.x, bx1.x), B1I = pk(bx1.y, bx1.y);

    // ---- SIC (packed): reload raw channel from smem, cancel, recombine ----
    ulonglong2 cbA0 = pst[c0 ? 0 : 2][tid];
    ulonglong2 cbA1 = pst[c0 ? 1 : 3][tid];
    ulonglong2 cbB0 = pst[c0 ? 4 : 6][tid];
    ulonglong2 cbB1 = pst[c0 ? 5 : 7][tid];
    ulonglong2 wA0  = pst[c0 ? 2 : 0][tid];
    ulonglong2 wA1  = pst[c0 ? 3 : 1][tid];
    ulonglong2 wB0  = pst[c0 ? 6 : 4][tid];
    ulonglong2 wB1  = pst[c0 ? 7 : 5][tid];
    u64 g0R = fadd2(wA0.x, wB0.x), g0I = fadd2(wA0.y, wB0.y);
    u64 g1R = fadd2(wA1.x, wB1.x), g1I = fadd2(wA1.y, wB1.y);

    // eA = cbA0*bx0 + cbA1*bx1
    u64 eAr = fsub2(dot2(cbA0.x,B0R, cbA1.x,B1R), dot2(cbA0.y,B0I, cbA1.y,B1I));
    u64 eAi = dot4(cbA0.x,B0I, cbA0.y,B0R, cbA1.x,B1I, cbA1.y,B1R);
    // eB = cbB0*(-conj(bx1)) + cbB1*conj(bx0)
    u64 eBr = fsub2(dot2(cbB1.x,B0R, cbB1.y,B0I), dot2(cbB0.x,B1R, cbB0.y,B1I));
    u64 eBi = fsub2(dot2(cbB0.x,B1I, cbB1.y,B0R), dot2(cbB0.y,B1R, cbB1.x,B0I));
    u64 rnAr = fsub2(yAr, eAr), rnAi = fsub2(yAi, eAi);
    u64 rnBr = fsub2(yBr, eBr), rnBi = fsub2(yBi, eBi);

    // t0 = conj(g0)*rnA + g1*conj(rnB); t1 = conj(g1)*rnA - g0*conj(rnB)
    float2 t0, t1;
    t0.x = usum(dot4(g0R,rnAr, g0I,rnAi, g1R,rnBr, g1I,rnBi));
    t0.y = usum(fsub2(dot2(g0R,rnAi, g1I,rnBr), dot2(g0I,rnAr, g1R,rnBi)));
    t1.x = usum(fsub2(dot2(g1R,rnAr, g1I,rnAi), dot2(g0R,rnBr, g0I,rnBi)));
    t1.y = usum(fsub2(dot2(g1R,rnAi, g0R,rnBi), dot2(g1I,rnAr, g0I,rnBr)));
    RED8(t0.x); RED8(t0.y); RED8(t1.x); RED8(t1.y);

    // g summed = 2x avg; true gain = betahat/4 -> y = 2*that/betahat
    const float invG = 2.0f / (c0 ? beta : alpha);
    float2 pn0, pn1; int ibn0, ibn1;
    hd16(cscl(t0, invG), TFULL, pn0, ibn0);
    hd16(cscl(t1, invG), TFULL, pn1, ibn1);

    // final stream assignments
    const int bb0 = c0 ? ib0 : ib2;   // better bits sym A
    const int bb1 = c0 ? ib1 : ib3;   // better bits sym B
    const int b0A = c0 ? bb0  : ibn0; // bits0 (stream 0)
    const int b0B = c0 ? bb1  : ibn1;
    const int b1A = c0 ? ibn0 : bb0;  // bits1 (stream 1)
    const int b1B = c0 ? ibn1 : bb1;

    // ---- outputs (streaming stores): bits0 | bits1 | gains0 | gains1 | nvar ----
    float* bits0 = out;
    float* bits1 = out + NBITS0;
    float* g0out = out + 2 * NBITS0;
    float* g1out = out + 2 * NBITS0 + NGAIN;

    const unsigned sym0 = 2u * p;
    const unsigned bbase = bf*48u + sym0*4u;     // float4-aligned

    if (j < 4) {
        int nib = (j == 0) ? b0A : (j == 1) ? b0B : (j == 2) ? b1A : b1B;
        float4 v = make_float4((float)( nib       & 1), (float)((nib >> 1) & 1),
                               (float)((nib >> 2) & 1), (float)((nib >> 3) & 1));
        float* base = (j < 2) ? bits0 : bits1;
        __stcs((float4*)(base + bbase + ((j & 1) << 2)), v);
    } else if (j == 4) {
        float g = alpha * 0.25f;      // true gain (sum -> avg scale)
        __stcs((float2*)(g0out + bf*12u + sym0), make_float2(g, g));
    } else if (j == 5) {
        float g = beta * 0.25f;
        __stcs((float2*)(g1out + bf*12u + sym0), make_float2(g, g));
    }

    if (blockIdx.x == 0 && tid == 0)
        out[2 * (NBITS0 + NGAIN)] = 0.4f;    // nvar scalar
}

extern "C" void kernel_launch(void* const* d_in, const int* in_sizes, int n_in,
                              void* d_out, int out_size) {
    const float* ryR = (const float*)d_in[0];
    const float* ryI = (const float*)d_in[1];
    const float* hR  = (const float*)d_in[2];
    const float* hI  = (const float*)d_in[3];
    float* out = (float*)d_out;

    // total pairs = 65536*6 = 393216; 4 pairs/warp, 8 warps/block -> 12288 blocks
    const int total_pairs = BF_TOT * PAIRS;
    const int blocks = total_pairs / 32;   // 32 pairs per 256-thread block
    mc_ncjt_kernel<<<blocks, 256>>>(ryR, ryI, hR, hI, out);
}